// round 15
// baseline (speedup 1.0000x reference)
#include <cuda_runtime.h>
#include <cuda_fp16.h>
#include <cuda_bf16.h>
#include <cstdint>

#define NN 10000
#define NE 640000
#define D 128
#define H 8

// ---------------- scratch (no allocations allowed) ----------------
// g_wV / g_z start zeroed (module load) and are re-zeroed by norm_kernel
// after consumption each replay, so no per-launch memset is needed.
__device__ __half g_Qh[NN * D];
__device__ __half g_Kh[NN * D];
__device__ __half g_Vh[NN * D];
__device__ float g_wV[NN * D];
__device__ float g_z[NN * H];
// We fp16 B-fragments, n8 pairs packed: [kb(8)][p(8)][lane(32)] -> {b0,b1,b0',b1'}
__device__ uint4 g_BfragE[8][8][32];
// WQ/WK/WV bf16 hi/lo B-fragments: [w(3)][img(2)][kb(8)][n8(16)][lane(32)] -> {b0,b1}
__device__ uint2 g_BfragN[3][2][8][16][32];

__device__ __forceinline__ uint32_t smem_u32(const void* p) {
    uint32_t a;
    asm("{ .reg .u64 t; cvta.to.shared.u64 t, %1; cvt.u32.u64 %0, t; }" : "=r"(a) : "l"(p));
    return a;
}

#define LDSM4(r0, r1, r2, r3, a) \
    asm volatile("ldmatrix.sync.aligned.m8n8.x4.shared.b16 {%0,%1,%2,%3}, [%4];" \
        : "=r"(r0), "=r"(r1), "=r"(r2), "=r"(r3) : "r"(a))

#define MMA16816F(c, a0, a1, a2, a3, b0, b1) \
    asm volatile("mma.sync.aligned.m16n8k16.row.col.f32.f16.f16.f32 " \
        "{%0,%1,%2,%3}, {%4,%5,%6,%7}, {%8,%9}, {%0,%1,%2,%3};" \
        : "+f"((c)[0]), "+f"((c)[1]), "+f"((c)[2]), "+f"((c)[3]) \
        : "r"(a0), "r"(a1), "r"(a2), "r"(a3), "r"(b0), "r"(b1))

#define MMA16816B(c, a0, a1, a2, a3, b0, b1) \
    asm volatile("mma.sync.aligned.m16n8k16.row.col.f32.bf16.bf16.f32 " \
        "{%0,%1,%2,%3}, {%4,%5,%6,%7}, {%8,%9}, {%0,%1,%2,%3};" \
        : "+f"((c)[0]), "+f"((c)[1]), "+f"((c)[2]), "+f"((c)[3]) \
        : "r"(a0), "r"(a1), "r"(a2), "r"(a3), "r"(b0), "r"(b1))

// ---------------- setup: weight fragments only ----------------
__global__ __launch_bounds__(512)
void setup_kernel(const float* __restrict__ WQ, const float* __restrict__ WK,
                  const float* __restrict__ WV, const float* __restrict__ We) {
    int i = blockIdx.x * blockDim.x + threadIdx.x;

    if (i < 2048) {
        int kb = i >> 8, p = (i >> 5) & 7, lane = i & 31;
        int k0 = kb * 16 + 2 * (lane & 3);
        int rsel = lane >> 2;
        uint32_t v[4];
#pragma unroll
        for (int half = 0; half < 2; ++half) {
            int n = (2 * p + half) * 8 + rsel;
            __half2 p0 = __halves2half2(__float2half(We[k0 * 128 + n]),
                                        __float2half(We[(k0 + 1) * 128 + n]));
            __half2 p1 = __halves2half2(__float2half(We[(k0 + 8) * 128 + n]),
                                        __float2half(We[(k0 + 9) * 128 + n]));
            v[half * 2 + 0] = *(uint32_t*)&p0;
            v[half * 2 + 1] = *(uint32_t*)&p1;
        }
        g_BfragE[kb][p][lane] = make_uint4(v[0], v[1], v[2], v[3]);
    } else if (i < 2048 + 24576) {
        int j = i - 2048;
        int w = j >> 13;
        int r = j & 8191;
        int img = r >> 12;
        int rr = r & 4095;
        int kb = rr >> 9, n8 = (rr >> 5) & 15, lane = rr & 31;
        const float* W = (w == 0) ? WQ : (w == 1) ? WK : WV;
        int n = n8 * 8 + (lane >> 2);
        int k0 = kb * 16 + 2 * (lane & 3);
        float f[4] = { W[k0 * 128 + n], W[(k0 + 1) * 128 + n],
                       W[(k0 + 8) * 128 + n], W[(k0 + 9) * 128 + n] };
        __nv_bfloat16 v[4];
#pragma unroll
        for (int t = 0; t < 4; ++t) {
            __nv_bfloat16 h = __float2bfloat16(f[t]);
            v[t] = (img == 0) ? h : __float2bfloat16(f[t] - __bfloat162float(h));
        }
        __nv_bfloat162 p0(v[0], v[1]), p1(v[2], v[3]);
        g_BfragN[w][img][kb][n8][lane] = make_uint2(*(uint32_t*)&p0, *(uint32_t*)&p1);
    }
}

// ---------------- node projection via bf16 3-pass mma, fp16 Ds + fp16 output ----------------
// smem padded: 2 CTAs/SM is load-bearing (R9 regression at 4 CTAs/SM).
#define PH 136
#define SM_NODE_TOTAL 69632

__global__ __launch_bounds__(512, 2)
void node_mma_kernel(const float* __restrict__ X) {
    extern __shared__ char smem[];
    uint32_t sb = smem_u32(smem);
    int tid = threadIdx.x, wid = tid >> 5, lane = tid & 31;
    int w = blockIdx.y;
    __half* Out = (w == 0) ? g_Qh : (w == 1) ? g_Kh : g_Vh;
    int rowBase = blockIdx.x << 7;

    {
        int row0 = wid * 8;
        int chunk = lane >> 1, half = lane & 1;
#pragma unroll
        for (int j = 0; j < 8; ++j) {
            int row = row0 + j;
            int gr = rowBase + row; if (gr >= NN) gr = NN - 1;
            float4 v = *(const float4*)&X[(size_t)gr * D + lane * 4];
            __nv_bfloat16 h0 = __float2bfloat16(v.x), h1 = __float2bfloat16(v.y);
            __nv_bfloat16 h2 = __float2bfloat16(v.z), h3 = __float2bfloat16(v.w);
            __nv_bfloat16 l0 = __float2bfloat16(v.x - __bfloat162float(h0));
            __nv_bfloat16 l1 = __float2bfloat16(v.y - __bfloat162float(h1));
            __nv_bfloat16 l2 = __float2bfloat16(v.z - __bfloat162float(h2));
            __nv_bfloat16 l3 = __float2bfloat16(v.w - __bfloat162float(h3));
            __nv_bfloat162 hp0(h0, h1), hp1(h2, h3), lp0(l0, l1), lp1(l2, l3);
            uint32_t off = (uint32_t)(row * 256 + ((chunk ^ (row & 7)) * 16) + half * 8);
            *(uint2*)(smem + off) = make_uint2(*(uint32_t*)&hp0, *(uint32_t*)&hp1);
            *(uint2*)(smem + 32768 + off) = make_uint2(*(uint32_t*)&lp0, *(uint32_t*)&lp1);
        }
    }
    int wm = wid >> 2, wn = wid & 3;
    // group-scope barrier: warp wid converts rows wid*8..+7, read only by group wm=wid>>2
    asm volatile("bar.sync %0, 128;" :: "r"(1 + wm) : "memory");

    float c[2][4][4];
#pragma unroll
    for (int m = 0; m < 2; ++m)
#pragma unroll
        for (int n = 0; n < 4; ++n)
#pragma unroll
            for (int j = 0; j < 4; ++j) c[m][n][j] = 0.f;

    int ar = (lane & 7) + ((lane >> 3) & 1) * 8;
    int aco = lane >> 4;
    int axr = lane & 7;
    uint32_t aBase = sb + (uint32_t)((wm * 32 + ar) * 256);

#pragma unroll
    for (int kb = 0; kb < 8; ++kb) {
        uint32_t au = (uint32_t)((2 * kb + aco) ^ axr) * 16;
        uint32_t Af[2][4];
        LDSM4(Af[0][0], Af[0][1], Af[0][2], Af[0][3], aBase + au);
        LDSM4(Af[1][0], Af[1][1], Af[1][2], Af[1][3], aBase + 16 * 256 + au);

        uint2 Bh[4], Bl[4];
#pragma unroll
        for (int n = 0; n < 4; ++n) Bh[n] = g_BfragN[w][0][kb][wn * 4 + n][lane];
#pragma unroll
        for (int m = 0; m < 2; ++m)
#pragma unroll
            for (int n = 0; n < 4; ++n)
                MMA16816B(c[m][n], Af[m][0], Af[m][1], Af[m][2], Af[m][3], Bh[n].x, Bh[n].y);
#pragma unroll
        for (int n = 0; n < 4; ++n) Bl[n] = g_BfragN[w][1][kb][wn * 4 + n][lane];
#pragma unroll
        for (int m = 0; m < 2; ++m)
#pragma unroll
            for (int n = 0; n < 4; ++n)
                MMA16816B(c[m][n], Af[m][0], Af[m][1], Af[m][2], Af[m][3], Bl[n].x, Bl[n].y);

        LDSM4(Af[0][0], Af[0][1], Af[0][2], Af[0][3], aBase + 32768 + au);
        LDSM4(Af[1][0], Af[1][1], Af[1][2], Af[1][3], aBase + 32768 + 16 * 256 + au);
#pragma unroll
        for (int m = 0; m < 2; ++m)
#pragma unroll
            for (int n = 0; n < 4; ++n)
                MMA16816B(c[m][n], Af[m][0], Af[m][1], Af[m][2], Af[m][3], Bh[n].x, Bh[n].y);
    }
    __syncthreads();   // Ds aliases A: all LDSMs must drain block-wide

    __half* Ds = (__half*)smem;
    {
        int rq = lane >> 2, cq = (lane & 3) * 2;
#pragma unroll
        for (int m = 0; m < 2; ++m) {
            int r0 = wm * 32 + m * 16 + rq;
#pragma unroll
            for (int n = 0; n < 4; ++n) {
                int cc = (wn * 4 + n) * 8 + cq;
                *(__half2*)&Ds[r0 * PH + cc] = __floats2half2_rn(c[m][n][0], c[m][n][1]);
                *(__half2*)&Ds[(r0 + 8) * PH + cc] = __floats2half2_rn(c[m][n][2], c[m][n][3]);
            }
        }
    }
    __syncthreads();

    int ty = tid >> 4, tx = tid & 15;
#pragma unroll
    for (int i = 0; i < 4; ++i) {
        int er = ty * 4 + i;
        int gr = rowBase + er;
        if (gr < NN) {
            *(uint2*)&Out[(size_t)gr * D + tx * 4] = *(const uint2*)&Ds[er * PH + tx * 4];
            *(uint2*)&Out[(size_t)gr * D + 64 + tx * 4] = *(const uint2*)&Ds[er * PH + 64 + tx * 4];
        }
    }
}

// ---------------- fused edge kernel v11: 2 tiles per CTA, disjoint Ds, group barriers ----------------
// smem: [0] src[128], [512] dst[128], [1024] A fp16 (32KB), [33792] Ds fp16 (34816B)
// total 68608, padded to 70656 (2 CTAs/SM cap).
#define SM_SRC  0
#define SM_DST  512
#define SM_A    1024
#define SM_DS   33792
#define SM_EDGE_TOTAL 70656
#define TILE 128
#define TILES_PER_CTA 2

__global__ __launch_bounds__(512, 2)
void edge_mma_kernel(const float* __restrict__ Ef,
                     const int* __restrict__ src, const int* __restrict__ dst,
                     float* __restrict__ e_out) {
    extern __shared__ char smem[];
    uint32_t sb = smem_u32(smem);
    int tid = threadIdx.x, wid = tid >> 5, lane = tid & 31;
    int wm = wid >> 2, wn = wid & 3;

    int ar = (lane & 7) + ((lane >> 3) & 1) * 8;
    int aco = lane >> 4;
    int axr = lane & 7;
    uint32_t aBase = sb + SM_A + (uint32_t)((wm * 32 + ar) * 256);
    __half* Ds = (__half*)(smem + SM_DS);
    const int* s_src = (const int*)(smem + SM_SRC);
    const int* s_dst = (const int*)(smem + SM_DST);

    const float isd = 0.25f;
    int ty = tid >> 4, tx = tid & 15;
    int ca = tx << 2;
    int cb = 64 + ca;

#pragma unroll
    for (int t = 0; t < TILES_PER_CTA; ++t) {
        int rowBase = (blockIdx.x * TILES_PER_CTA + t) << 7;

        if (t > 0) __syncthreads();   // tile t-1 epilogue reads of src/dst/Ds must drain

        if (tid < 128) {
            ((int*)(smem + SM_SRC))[tid] = src[rowBase + tid];
            ((int*)(smem + SM_DST))[tid] = dst[rowBase + tid];
        }

        // convert Ef tile (128x128 f32) -> fp16 swizzled image (group-local rows)
        {
            int row0 = wid * 8;
            int chunk = lane >> 1, half = lane & 1;
#pragma unroll
            for (int j = 0; j < 8; ++j) {
                int row = row0 + j;
                float4 v = __ldcs((const float4*)&Ef[(size_t)(rowBase + row) * D + lane * 4]);
                __half2 p0 = __halves2half2(__float2half(v.x), __float2half(v.y));
                __half2 p1 = __halves2half2(__float2half(v.z), __float2half(v.w));
                uint32_t off = (uint32_t)(row * 256 + ((chunk ^ (row & 7)) * 16) + half * 8);
                *(uint2*)(smem + SM_A + off) = make_uint2(*(uint32_t*)&p0, *(uint32_t*)&p1);
            }
        }
        asm volatile("bar.sync %0, 128;" :: "r"(1 + wm) : "memory");

        float c[2][4][4];
#pragma unroll
        for (int m = 0; m < 2; ++m)
#pragma unroll
            for (int n = 0; n < 4; ++n)
#pragma unroll
                for (int j = 0; j < 4; ++j) c[m][n][j] = 0.f;

#pragma unroll
        for (int kb = 0; kb < 8; ++kb) {
            uint32_t au = (uint32_t)((2 * kb + aco) ^ axr) * 16;
            uint32_t Af[2][4];
            LDSM4(Af[0][0], Af[0][1], Af[0][2], Af[0][3], aBase + au);
            LDSM4(Af[1][0], Af[1][1], Af[1][2], Af[1][3], aBase + 16 * 256 + au);

            uint4 Bq0 = g_BfragE[kb][wn * 2 + 0][lane];
            uint4 Bq1 = g_BfragE[kb][wn * 2 + 1][lane];
#pragma unroll
            for (int m = 0; m < 2; ++m) {
                MMA16816F(c[m][0], Af[m][0], Af[m][1], Af[m][2], Af[m][3], Bq0.x, Bq0.y);
                MMA16816F(c[m][1], Af[m][0], Af[m][1], Af[m][2], Af[m][3], Bq0.z, Bq0.w);
                MMA16816F(c[m][2], Af[m][0], Af[m][1], Af[m][2], Af[m][3], Bq1.x, Bq1.y);
                MMA16816F(c[m][3], Af[m][0], Af[m][1], Af[m][2], Af[m][3], Bq1.z, Bq1.w);
            }
        }

        // Ds disjoint from A -> no barrier between MMA and staging
        {
            int rq = lane >> 2, cq = (lane & 3) * 2;
#pragma unroll
            for (int m = 0; m < 2; ++m) {
                int r0 = wm * 32 + m * 16 + rq;
#pragma unroll
                for (int n = 0; n < 4; ++n) {
                    int cc = (wn * 4 + n) * 8 + cq;
                    *(__half2*)&Ds[r0 * PH + cc] = __floats2half2_rn(c[m][n][0], c[m][n][1]);
                    *(__half2*)&Ds[(r0 + 8) * PH + cc] = __floats2half2_rn(c[m][n][2], c[m][n][3]);
                }
            }
        }
        __syncthreads();   // epilogue reads Ds/src/dst produced by all warps

        // ---- epilogue: fp16 gathers + fp16 Ds, coalescing-exact mapping ----
#pragma unroll
        for (int i = 0; i < 4; ++i) {
            int er = ty * 4 + i;
            int e = rowBase + er;
            int sn = s_src[er], dn = s_dst[er];

            const __half* Krow = g_Kh + (size_t)sn * D;
            const __half* Qrow = g_Qh + (size_t)dn * D;
            const __half* Vrow = g_Vh + (size_t)sn * D;

            uint2 ku_a = *(const uint2*)(Krow + ca), ku_b = *(const uint2*)(Krow + cb);
            uint2 qu_a = *(const uint2*)(Qrow + ca), qu_b = *(const uint2*)(Qrow + cb);

            float2 k0 = __half22float2(*(__half2*)&ku_a.x), k1 = __half22float2(*(__half2*)&ku_a.y);
            float2 k2 = __half22float2(*(__half2*)&ku_b.x), k3 = __half22float2(*(__half2*)&ku_b.y);
            float2 q0 = __half22float2(*(__half2*)&qu_a.x), q1 = __half22float2(*(__half2*)&qu_a.y);
            float2 q2 = __half22float2(*(__half2*)&qu_b.x), q3 = __half22float2(*(__half2*)&qu_b.y);

            uint2 pu_a = *(const uint2*)&Ds[er * PH + ca];
            uint2 pu_b = *(const uint2*)&Ds[er * PH + cb];
            float2 p0 = __half22float2(*(__half2*)&pu_a.x), p1 = __half22float2(*(__half2*)&pu_a.y);
            float2 p2 = __half22float2(*(__half2*)&pu_b.x), p3 = __half22float2(*(__half2*)&pu_b.y);

            float sa[4], sbv[4];
            float parta, partb;
            {
                float kq0 = fminf(fmaxf(k0.x * q0.x * isd, -5.f), 5.f);
                float kq1 = fminf(fmaxf(k0.y * q0.y * isd, -5.f), 5.f);
                float kq2 = fminf(fmaxf(k1.x * q1.x * isd, -5.f), 5.f);
                float kq3 = fminf(fmaxf(k1.y * q1.y * isd, -5.f), 5.f);
                sa[0] = kq0 * p0.x; sa[1] = kq1 * p0.y; sa[2] = kq2 * p1.x; sa[3] = kq3 * p1.y;
                parta = sa[0] + sa[1] + sa[2] + sa[3];
            }
            {
                float kq0 = fminf(fmaxf(k2.x * q2.x * isd, -5.f), 5.f);
                float kq1 = fminf(fmaxf(k2.y * q2.y * isd, -5.f), 5.f);
                float kq2 = fminf(fmaxf(k3.x * q3.x * isd, -5.f), 5.f);
                float kq3 = fminf(fmaxf(k3.y * q3.y * isd, -5.f), 5.f);
                sbv[0] = kq0 * p2.x; sbv[1] = kq1 * p2.y; sbv[2] = kq2 * p3.x; sbv[3] = kq3 * p3.y;
                partb = sbv[0] + sbv[1] + sbv[2] + sbv[3];
            }

            __stcs((float4*)&e_out[(size_t)e * D + ca], make_float4(sa[0], sa[1], sa[2], sa[3]));
            __stcs((float4*)&e_out[(size_t)e * D + cb], make_float4(sbv[0], sbv[1], sbv[2], sbv[3]));

            parta += __shfl_xor_sync(0xffffffffu, parta, 1);
            parta += __shfl_xor_sync(0xffffffffu, parta, 2);
            partb += __shfl_xor_sync(0xffffffffu, partb, 1);
            partb += __shfl_xor_sync(0xffffffffu, partb, 2);
            float s1 = __expf(fminf(fmaxf(parta, -5.f), 5.f));
            float s2 = __expf(fminf(fmaxf(partb, -5.f), 5.f));

            uint2 vu_a = *(const uint2*)(Vrow + ca), vu_b = *(const uint2*)(Vrow + cb);
            float2 v0 = __half22float2(*(__half2*)&vu_a.x), v1 = __half22float2(*(__half2*)&vu_a.y);
            float2 v2 = __half22float2(*(__half2*)&vu_b.x), v3 = __half22float2(*(__half2*)&vu_b.y);

            float* w = &g_wV[dn * D + ca];
            asm volatile("red.global.add.v4.f32 [%0], {%1,%2,%3,%4};"
                         :: "l"(w), "f"(v0.x * s1), "f"(v0.y * s1), "f"(v1.x * s1), "f"(v1.y * s1)
                         : "memory");
            asm volatile("red.global.add.v4.f32 [%0], {%1,%2,%3,%4};"
                         :: "l"(w + 64), "f"(v2.x * s2), "f"(v2.y * s2), "f"(v3.x * s2), "f"(v3.y * s2)
                         : "memory");
            if ((tx & 3) == 0) {
                atomicAdd(&g_z[dn * H + (tx >> 2)], s1);
                atomicAdd(&g_z[dn * H + 4 + (tx >> 2)], s2);
            }
        }
    }
}

// ---------------- normalize (float4) + self-zero accumulators ----------------
__global__ __launch_bounds__(512)
void norm_kernel(float* __restrict__ h_out) {
    int i = blockIdx.x * blockDim.x + threadIdx.x;   // float4 index
    if (i < NN * D / 4) {
        int base = i * 4;
        int n = base >> 7;
        int hh = (base & 127) >> 4;
        float z = g_z[n * H + hh] + 1e-6f;
        float4 wv = ((const float4*)g_wV)[i];
        ((float4*)h_out)[i] = make_float4(wv.x / z, wv.y / z, wv.z / z, wv.w / z);
        // re-zero for next replay (warp covers one node row; z reads precede these stores)
        ((float4*)g_wV)[i] = make_float4(0.f, 0.f, 0.f, 0.f);
        if ((i & 3) == 0) g_z[n * H + hh] = 0.f;
    }
}

// ---------------- launch ----------------
extern "C" void kernel_launch(void* const* d_in, const int* in_sizes, int n_in,
                              void* d_out, int out_size) {
    const float* node_feats = (const float*)d_in[0];
    const float* edge_feats = (const float*)d_in[1];
    const int* src = (const int*)d_in[2];
    const int* dst = (const int*)d_in[3];
    const float* WQ = (const float*)d_in[4];
    const float* WK = (const float*)d_in[5];
    const float* WV = (const float*)d_in[6];
    const float* We = (const float*)d_in[7];

    float* out = (float*)d_out;
    float* h_out = out;                  // [NN, H, DH]
    float* e_out = out + (size_t)NN * D; // [NE, H, DH]

    static int smem_set = 0;
    if (!smem_set) {
        cudaFuncSetAttribute(edge_mma_kernel, cudaFuncAttributeMaxDynamicSharedMemorySize, SM_EDGE_TOTAL);
        cudaFuncSetAttribute(node_mma_kernel, cudaFuncAttributeMaxDynamicSharedMemorySize, SM_NODE_TOTAL);
        smem_set = 1;
    }

    setup_kernel<<<52, 512>>>(WQ, WK, WV, We);

    dim3 gn((NN + 127) / 128, 3);
    node_mma_kernel<<<gn, 512, SM_NODE_TOTAL>>>(node_feats);

    edge_mma_kernel<<<NE / (TILE * TILES_PER_CTA), 512, SM_EDGE_TOTAL>>>(edge_feats, src, dst, e_out);

    norm_kernel<<<(NN * D / 4 + 511) / 512, 512>>>(h_out);
}

// round 16
// speedup vs baseline: 1.0581x; 1.0581x over previous
#include <cuda_runtime.h>
#include <cuda_fp16.h>
#include <cuda_bf16.h>
#include <cstdint>

#define NN 10000
#define NE 640000
#define D 128
#define H 8

// ---------------- scratch (no allocations allowed) ----------------
// g_wV / g_z start zeroed (module load) and are re-zeroed by norm_kernel
// after consumption each replay, so no per-launch memset is needed.
__device__ __half g_Qh[NN * D];
__device__ __half g_Kh[NN * D];
__device__ __half g_Vh[NN * D];
__device__ float g_wV[NN * D];
__device__ float g_z[NN * H];
// We fp16 B-fragments, n8 pairs packed: [kb(8)][p(8)][lane(32)] -> {b0,b1,b0',b1'}
__device__ uint4 g_BfragE[8][8][32];
// WQ/WK/WV bf16 hi/lo B-fragments: [w(3)][img(2)][kb(8)][n8(16)][lane(32)] -> {b0,b1}
__device__ uint2 g_BfragN[3][2][8][16][32];

__device__ __forceinline__ uint32_t smem_u32(const void* p) {
    uint32_t a;
    asm("{ .reg .u64 t; cvta.to.shared.u64 t, %1; cvt.u32.u64 %0, t; }" : "=r"(a) : "l"(p));
    return a;
}

#define LDSM4(r0, r1, r2, r3, a) \
    asm volatile("ldmatrix.sync.aligned.m8n8.x4.shared.b16 {%0,%1,%2,%3}, [%4];" \
        : "=r"(r0), "=r"(r1), "=r"(r2), "=r"(r3) : "r"(a))

#define MMA16816F(c, a0, a1, a2, a3, b0, b1) \
    asm volatile("mma.sync.aligned.m16n8k16.row.col.f32.f16.f16.f32 " \
        "{%0,%1,%2,%3}, {%4,%5,%6,%7}, {%8,%9}, {%0,%1,%2,%3};" \
        : "+f"((c)[0]), "+f"((c)[1]), "+f"((c)[2]), "+f"((c)[3]) \
        : "r"(a0), "r"(a1), "r"(a2), "r"(a3), "r"(b0), "r"(b1))

#define MMA16816B(c, a0, a1, a2, a3, b0, b1) \
    asm volatile("mma.sync.aligned.m16n8k16.row.col.f32.bf16.bf16.f32 " \
        "{%0,%1,%2,%3}, {%4,%5,%6,%7}, {%8,%9}, {%0,%1,%2,%3};" \
        : "+f"((c)[0]), "+f"((c)[1]), "+f"((c)[2]), "+f"((c)[3]) \
        : "r"(a0), "r"(a1), "r"(a2), "r"(a3), "r"(b0), "r"(b1))

// ---------------- setup: weight fragments only ----------------
__global__ __launch_bounds__(512)
void setup_kernel(const float* __restrict__ WQ, const float* __restrict__ WK,
                  const float* __restrict__ WV, const float* __restrict__ We) {
    int i = blockIdx.x * blockDim.x + threadIdx.x;

    if (i < 2048) {
        int kb = i >> 8, p = (i >> 5) & 7, lane = i & 31;
        int k0 = kb * 16 + 2 * (lane & 3);
        int rsel = lane >> 2;
        uint32_t v[4];
#pragma unroll
        for (int half = 0; half < 2; ++half) {
            int n = (2 * p + half) * 8 + rsel;
            __half2 p0 = __halves2half2(__float2half(We[k0 * 128 + n]),
                                        __float2half(We[(k0 + 1) * 128 + n]));
            __half2 p1 = __halves2half2(__float2half(We[(k0 + 8) * 128 + n]),
                                        __float2half(We[(k0 + 9) * 128 + n]));
            v[half * 2 + 0] = *(uint32_t*)&p0;
            v[half * 2 + 1] = *(uint32_t*)&p1;
        }
        g_BfragE[kb][p][lane] = make_uint4(v[0], v[1], v[2], v[3]);
    } else if (i < 2048 + 24576) {
        int j = i - 2048;
        int w = j >> 13;
        int r = j & 8191;
        int img = r >> 12;
        int rr = r & 4095;
        int kb = rr >> 9, n8 = (rr >> 5) & 15, lane = rr & 31;
        const float* W = (w == 0) ? WQ : (w == 1) ? WK : WV;
        int n = n8 * 8 + (lane >> 2);
        int k0 = kb * 16 + 2 * (lane & 3);
        float f[4] = { W[k0 * 128 + n], W[(k0 + 1) * 128 + n],
                       W[(k0 + 8) * 128 + n], W[(k0 + 9) * 128 + n] };
        __nv_bfloat16 v[4];
#pragma unroll
        for (int t = 0; t < 4; ++t) {
            __nv_bfloat16 h = __float2bfloat16(f[t]);
            v[t] = (img == 0) ? h : __float2bfloat16(f[t] - __bfloat162float(h));
        }
        __nv_bfloat162 p0(v[0], v[1]), p1(v[2], v[3]);
        g_BfragN[w][img][kb][n8][lane] = make_uint2(*(uint32_t*)&p0, *(uint32_t*)&p1);
    }
}

// ---------------- node projection via bf16 3-pass mma, fp16 Ds + fp16 output ----------------
// smem padded: 2 CTAs/SM is load-bearing (R9 regression at 4 CTAs/SM).
#define PH 136
#define SM_NODE_TOTAL 69632

__global__ __launch_bounds__(512, 2)
void node_mma_kernel(const float* __restrict__ X) {
    extern __shared__ char smem[];
    uint32_t sb = smem_u32(smem);
    int tid = threadIdx.x, wid = tid >> 5, lane = tid & 31;
    int w = blockIdx.y;
    __half* Out = (w == 0) ? g_Qh : (w == 1) ? g_Kh : g_Vh;
    int rowBase = blockIdx.x << 7;

    {
        int row0 = wid * 8;
        int chunk = lane >> 1, half = lane & 1;
#pragma unroll
        for (int j = 0; j < 8; ++j) {
            int row = row0 + j;
            int gr = rowBase + row; if (gr >= NN) gr = NN - 1;
            float4 v = *(const float4*)&X[(size_t)gr * D + lane * 4];
            __nv_bfloat16 h0 = __float2bfloat16(v.x), h1 = __float2bfloat16(v.y);
            __nv_bfloat16 h2 = __float2bfloat16(v.z), h3 = __float2bfloat16(v.w);
            __nv_bfloat16 l0 = __float2bfloat16(v.x - __bfloat162float(h0));
            __nv_bfloat16 l1 = __float2bfloat16(v.y - __bfloat162float(h1));
            __nv_bfloat16 l2 = __float2bfloat16(v.z - __bfloat162float(h2));
            __nv_bfloat16 l3 = __float2bfloat16(v.w - __bfloat162float(h3));
            __nv_bfloat162 hp0(h0, h1), hp1(h2, h3), lp0(l0, l1), lp1(l2, l3);
            uint32_t off = (uint32_t)(row * 256 + ((chunk ^ (row & 7)) * 16) + half * 8);
            *(uint2*)(smem + off) = make_uint2(*(uint32_t*)&hp0, *(uint32_t*)&hp1);
            *(uint2*)(smem + 32768 + off) = make_uint2(*(uint32_t*)&lp0, *(uint32_t*)&lp1);
        }
    }
    int wm = wid >> 2, wn = wid & 3;
    // group-scope barrier: warp wid converts rows wid*8..+7, read only by group wm=wid>>2
    asm volatile("bar.sync %0, 128;" :: "r"(1 + wm) : "memory");

    float c[2][4][4];
#pragma unroll
    for (int m = 0; m < 2; ++m)
#pragma unroll
        for (int n = 0; n < 4; ++n)
#pragma unroll
            for (int j = 0; j < 4; ++j) c[m][n][j] = 0.f;

    int ar = (lane & 7) + ((lane >> 3) & 1) * 8;
    int aco = lane >> 4;
    int axr = lane & 7;
    uint32_t aBase = sb + (uint32_t)((wm * 32 + ar) * 256);

#pragma unroll
    for (int kb = 0; kb < 8; ++kb) {
        uint32_t au = (uint32_t)((2 * kb + aco) ^ axr) * 16;
        uint32_t Af[2][4];
        LDSM4(Af[0][0], Af[0][1], Af[0][2], Af[0][3], aBase + au);
        LDSM4(Af[1][0], Af[1][1], Af[1][2], Af[1][3], aBase + 16 * 256 + au);

        uint2 Bh[4], Bl[4];
#pragma unroll
        for (int n = 0; n < 4; ++n) Bh[n] = g_BfragN[w][0][kb][wn * 4 + n][lane];
#pragma unroll
        for (int m = 0; m < 2; ++m)
#pragma unroll
            for (int n = 0; n < 4; ++n)
                MMA16816B(c[m][n], Af[m][0], Af[m][1], Af[m][2], Af[m][3], Bh[n].x, Bh[n].y);
#pragma unroll
        for (int n = 0; n < 4; ++n) Bl[n] = g_BfragN[w][1][kb][wn * 4 + n][lane];
#pragma unroll
        for (int m = 0; m < 2; ++m)
#pragma unroll
            for (int n = 0; n < 4; ++n)
                MMA16816B(c[m][n], Af[m][0], Af[m][1], Af[m][2], Af[m][3], Bl[n].x, Bl[n].y);

        LDSM4(Af[0][0], Af[0][1], Af[0][2], Af[0][3], aBase + 32768 + au);
        LDSM4(Af[1][0], Af[1][1], Af[1][2], Af[1][3], aBase + 32768 + 16 * 256 + au);
#pragma unroll
        for (int m = 0; m < 2; ++m)
#pragma unroll
            for (int n = 0; n < 4; ++n)
                MMA16816B(c[m][n], Af[m][0], Af[m][1], Af[m][2], Af[m][3], Bh[n].x, Bh[n].y);
    }
    __syncthreads();   // Ds aliases A: all LDSMs must drain block-wide

    __half* Ds = (__half*)smem;
    {
        int rq = lane >> 2, cq = (lane & 3) * 2;
#pragma unroll
        for (int m = 0; m < 2; ++m) {
            int r0 = wm * 32 + m * 16 + rq;
#pragma unroll
            for (int n = 0; n < 4; ++n) {
                int cc = (wn * 4 + n) * 8 + cq;
                *(__half2*)&Ds[r0 * PH + cc] = __floats2half2_rn(c[m][n][0], c[m][n][1]);
                *(__half2*)&Ds[(r0 + 8) * PH + cc] = __floats2half2_rn(c[m][n][2], c[m][n][3]);
            }
        }
    }
    __syncthreads();

    int ty = tid >> 4, tx = tid & 15;
#pragma unroll
    for (int i = 0; i < 4; ++i) {
        int er = ty * 4 + i;
        int gr = rowBase + er;
        if (gr < NN) {
            *(uint2*)&Out[(size_t)gr * D + tx * 4] = *(const uint2*)&Ds[er * PH + tx * 4];
            *(uint2*)&Out[(size_t)gr * D + 64 + tx * 4] = *(const uint2*)&Ds[er * PH + 64 + tx * 4];
        }
    }
}

// ---------------- fused edge kernel v10 (R14): disjoint Ds + group barriers, 1 tile/CTA ----------------
// smem: [0] src[128], [512] dst[128], [1024] A fp16 (32KB), [33792] Ds fp16 (34816B)
// total 68608, padded to 70656 (2 CTAs/SM cap).
#define SM_SRC  0
#define SM_DST  512
#define SM_A    1024
#define SM_DS   33792
#define SM_EDGE_TOTAL 70656
#define TILE 128

__global__ __launch_bounds__(512, 2)
void edge_mma_kernel(const float* __restrict__ Ef,
                     const int* __restrict__ src, const int* __restrict__ dst,
                     float* __restrict__ e_out) {
    extern __shared__ char smem[];
    uint32_t sb = smem_u32(smem);
    int tid = threadIdx.x, wid = tid >> 5, lane = tid & 31;
    int rowBase = blockIdx.x << 7;

    if (tid < 128) {
        ((int*)(smem + SM_SRC))[tid] = src[rowBase + tid];
        ((int*)(smem + SM_DST))[tid] = dst[rowBase + tid];
    }

    // convert Ef tile (128x128 f32) -> fp16 swizzled image.
    // warp wid converts rows wid*8..+7 == exactly the rows its 4-warp group (wm=wid>>2)
    // will ldmatrix, so only a 128-thread named barrier is needed (not block-wide).
    {
        int row0 = wid * 8;
        int chunk = lane >> 1, half = lane & 1;
#pragma unroll
        for (int j = 0; j < 8; ++j) {
            int row = row0 + j;
            float4 v = __ldcs((const float4*)&Ef[(size_t)(rowBase + row) * D + lane * 4]);
            __half2 p0 = __halves2half2(__float2half(v.x), __float2half(v.y));
            __half2 p1 = __halves2half2(__float2half(v.z), __float2half(v.w));
            uint32_t off = (uint32_t)(row * 256 + ((chunk ^ (row & 7)) * 16) + half * 8);
            *(uint2*)(smem + SM_A + off) = make_uint2(*(uint32_t*)&p0, *(uint32_t*)&p1);
        }
    }
    int wm = wid >> 2, wn = wid & 3;
    asm volatile("bar.sync %0, 128;" :: "r"(1 + wm) : "memory");

    float c[2][4][4];
#pragma unroll
    for (int m = 0; m < 2; ++m)
#pragma unroll
        for (int n = 0; n < 4; ++n)
#pragma unroll
            for (int j = 0; j < 4; ++j) c[m][n][j] = 0.f;

    int ar = (lane & 7) + ((lane >> 3) & 1) * 8;
    int aco = lane >> 4;
    int axr = lane & 7;
    uint32_t aBase = sb + SM_A + (uint32_t)((wm * 32 + ar) * 256);

#pragma unroll
    for (int kb = 0; kb < 8; ++kb) {
        uint32_t au = (uint32_t)((2 * kb + aco) ^ axr) * 16;
        uint32_t Af[2][4];
        LDSM4(Af[0][0], Af[0][1], Af[0][2], Af[0][3], aBase + au);
        LDSM4(Af[1][0], Af[1][1], Af[1][2], Af[1][3], aBase + 16 * 256 + au);

        uint4 Bq0 = g_BfragE[kb][wn * 2 + 0][lane];
        uint4 Bq1 = g_BfragE[kb][wn * 2 + 1][lane];
#pragma unroll
        for (int m = 0; m < 2; ++m) {
            MMA16816F(c[m][0], Af[m][0], Af[m][1], Af[m][2], Af[m][3], Bq0.x, Bq0.y);
            MMA16816F(c[m][1], Af[m][0], Af[m][1], Af[m][2], Af[m][3], Bq0.z, Bq0.w);
            MMA16816F(c[m][2], Af[m][0], Af[m][1], Af[m][2], Af[m][3], Bq1.x, Bq1.y);
            MMA16816F(c[m][3], Af[m][0], Af[m][1], Af[m][2], Af[m][3], Bq1.z, Bq1.w);
        }
    }

    // Ds is DISJOINT from A -> no barrier needed between MMA and staging:
    // each warp stores only its own fragments.
    __half* Ds = (__half*)(smem + SM_DS);
    {
        int rq = lane >> 2, cq = (lane & 3) * 2;
#pragma unroll
        for (int m = 0; m < 2; ++m) {
            int r0 = wm * 32 + m * 16 + rq;
#pragma unroll
            for (int n = 0; n < 4; ++n) {
                int cc = (wn * 4 + n) * 8 + cq;
                *(__half2*)&Ds[r0 * PH + cc] = __floats2half2_rn(c[m][n][0], c[m][n][1]);
                *(__half2*)&Ds[(r0 + 8) * PH + cc] = __floats2half2_rn(c[m][n][2], c[m][n][3]);
            }
        }
    }
    __syncthreads();   // epilogue reads Ds columns produced by all warps

    // ---- epilogue: fp16 gathers + fp16 Ds, coalescing-exact mapping ----
    const float isd = 0.25f;
    int ty = tid >> 4, tx = tid & 15;
    int ca = tx << 2;
    int cb = 64 + ca;
    const int* s_src = (const int*)(smem + SM_SRC);
    const int* s_dst = (const int*)(smem + SM_DST);

#pragma unroll
    for (int i = 0; i < 4; ++i) {
        int er = ty * 4 + i;
        int e = rowBase + er;
        int sn = s_src[er], dn = s_dst[er];

        const __half* Krow = g_Kh + (size_t)sn * D;
        const __half* Qrow = g_Qh + (size_t)dn * D;
        const __half* Vrow = g_Vh + (size_t)sn * D;

        uint2 ku_a = *(const uint2*)(Krow + ca), ku_b = *(const uint2*)(Krow + cb);
        uint2 qu_a = *(const uint2*)(Qrow + ca), qu_b = *(const uint2*)(Qrow + cb);

        float2 k0 = __half22float2(*(__half2*)&ku_a.x), k1 = __half22float2(*(__half2*)&ku_a.y);
        float2 k2 = __half22float2(*(__half2*)&ku_b.x), k3 = __half22float2(*(__half2*)&ku_b.y);
        float2 q0 = __half22float2(*(__half2*)&qu_a.x), q1 = __half22float2(*(__half2*)&qu_a.y);
        float2 q2 = __half22float2(*(__half2*)&qu_b.x), q3 = __half22float2(*(__half2*)&qu_b.y);

        uint2 pu_a = *(const uint2*)&Ds[er * PH + ca];
        uint2 pu_b = *(const uint2*)&Ds[er * PH + cb];
        float2 p0 = __half22float2(*(__half2*)&pu_a.x), p1 = __half22float2(*(__half2*)&pu_a.y);
        float2 p2 = __half22float2(*(__half2*)&pu_b.x), p3 = __half22float2(*(__half2*)&pu_b.y);

        float sa[4], sbv[4];
        float parta, partb;
        {
            float kq0 = fminf(fmaxf(k0.x * q0.x * isd, -5.f), 5.f);
            float kq1 = fminf(fmaxf(k0.y * q0.y * isd, -5.f), 5.f);
            float kq2 = fminf(fmaxf(k1.x * q1.x * isd, -5.f), 5.f);
            float kq3 = fminf(fmaxf(k1.y * q1.y * isd, -5.f), 5.f);
            sa[0] = kq0 * p0.x; sa[1] = kq1 * p0.y; sa[2] = kq2 * p1.x; sa[3] = kq3 * p1.y;
            parta = sa[0] + sa[1] + sa[2] + sa[3];
        }
        {
            float kq0 = fminf(fmaxf(k2.x * q2.x * isd, -5.f), 5.f);
            float kq1 = fminf(fmaxf(k2.y * q2.y * isd, -5.f), 5.f);
            float kq2 = fminf(fmaxf(k3.x * q3.x * isd, -5.f), 5.f);
            float kq3 = fminf(fmaxf(k3.y * q3.y * isd, -5.f), 5.f);
            sbv[0] = kq0 * p2.x; sbv[1] = kq1 * p2.y; sbv[2] = kq2 * p3.x; sbv[3] = kq3 * p3.y;
            partb = sbv[0] + sbv[1] + sbv[2] + sbv[3];
        }

        __stcs((float4*)&e_out[(size_t)e * D + ca], make_float4(sa[0], sa[1], sa[2], sa[3]));
        __stcs((float4*)&e_out[(size_t)e * D + cb], make_float4(sbv[0], sbv[1], sbv[2], sbv[3]));

        parta += __shfl_xor_sync(0xffffffffu, parta, 1);
        parta += __shfl_xor_sync(0xffffffffu, parta, 2);
        partb += __shfl_xor_sync(0xffffffffu, partb, 1);
        partb += __shfl_xor_sync(0xffffffffu, partb, 2);
        float s1 = __expf(fminf(fmaxf(parta, -5.f), 5.f));
        float s2 = __expf(fminf(fmaxf(partb, -5.f), 5.f));

        uint2 vu_a = *(const uint2*)(Vrow + ca), vu_b = *(const uint2*)(Vrow + cb);
        float2 v0 = __half22float2(*(__half2*)&vu_a.x), v1 = __half22float2(*(__half2*)&vu_a.y);
        float2 v2 = __half22float2(*(__half2*)&vu_b.x), v3 = __half22float2(*(__half2*)&vu_b.y);

        float* w = &g_wV[dn * D + ca];
        asm volatile("red.global.add.v4.f32 [%0], {%1,%2,%3,%4};"
                     :: "l"(w), "f"(v0.x * s1), "f"(v0.y * s1), "f"(v1.x * s1), "f"(v1.y * s1)
                     : "memory");
        asm volatile("red.global.add.v4.f32 [%0], {%1,%2,%3,%4};"
                     :: "l"(w + 64), "f"(v2.x * s2), "f"(v2.y * s2), "f"(v3.x * s2), "f"(v3.y * s2)
                     : "memory");
        if ((tx & 3) == 0) {
            atomicAdd(&g_z[dn * H + (tx >> 2)], s1);
            atomicAdd(&g_z[dn * H + 4 + (tx >> 2)], s2);
        }
    }
}

// ---------------- normalize (float4) + self-zero accumulators ----------------
__global__ __launch_bounds__(512)
void norm_kernel(float* __restrict__ h_out) {
    int i = blockIdx.x * blockDim.x + threadIdx.x;   // float4 index
    if (i < NN * D / 4) {
        int base = i * 4;
        int n = base >> 7;
        int hh = (base & 127) >> 4;
        float z = g_z[n * H + hh] + 1e-6f;
        float4 wv = ((const float4*)g_wV)[i];
        ((float4*)h_out)[i] = make_float4(wv.x / z, wv.y / z, wv.z / z, wv.w / z);
        // re-zero for next replay (warp covers one node row; z reads precede these stores)
        ((float4*)g_wV)[i] = make_float4(0.f, 0.f, 0.f, 0.f);
        if ((i & 3) == 0) g_z[n * H + hh] = 0.f;
    }
}

// ---------------- launch ----------------
extern "C" void kernel_launch(void* const* d_in, const int* in_sizes, int n_in,
                              void* d_out, int out_size) {
    const float* node_feats = (const float*)d_in[0];
    const float* edge_feats = (const float*)d_in[1];
    const int* src = (const int*)d_in[2];
    const int* dst = (const int*)d_in[3];
    const float* WQ = (const float*)d_in[4];
    const float* WK = (const float*)d_in[5];
    const float* WV = (const float*)d_in[6];
    const float* We = (const float*)d_in[7];

    float* out = (float*)d_out;
    float* h_out = out;                  // [NN, H, DH]
    float* e_out = out + (size_t)NN * D; // [NE, H, DH]

    static int smem_set = 0;
    if (!smem_set) {
        cudaFuncSetAttribute(edge_mma_kernel, cudaFuncAttributeMaxDynamicSharedMemorySize, SM_EDGE_TOTAL);
        cudaFuncSetAttribute(node_mma_kernel, cudaFuncAttributeMaxDynamicSharedMemorySize, SM_NODE_TOTAL);
        smem_set = 1;
    }

    setup_kernel<<<52, 512>>>(WQ, WK, WV, We);

    dim3 gn((NN + 127) / 128, 3);
    node_mma_kernel<<<gn, 512, SM_NODE_TOTAL>>>(node_feats);

    edge_mma_kernel<<<NE / TILE, 512, SM_EDGE_TOTAL>>>(edge_feats, src, dst, e_out);

    norm_kernel<<<(NN * D / 4 + 511) / 512, 512>>>(h_out);
}